// round 1
// baseline (speedup 1.0000x reference)
#include <cuda_runtime.h>
#include <cuda_bf16.h>
#include <cstdint>

#define Bsz 64
#define Ssz 256
#define Isz 128
#define Hsz 128
#define UNF 6

// ---------------- device scratch (no runtime allocation allowed) ----------------
__device__ float2  g_rab[Hsz*Hsz];      // recurrent (a,b): a=0.5*sigma, b=-0.5*sigma*mu, layout [src][dst]
__device__ float   g_rcs[Hsz*Hsz];      // recurrent signed weight 0.5*softplus(w)*erev, [src][dst]
__device__ float2  g_sab[Isz*Hsz];      // sensory (a',b') with input affine folded, [i][h]
__device__ float   g_scs[Isz*Hsz];      // sensory signed weight, [i][h]
__device__ float   g_numconst[Hsz];     // gl*vleak + sum(cs_rec) + sum(cs_sens)
__device__ float   g_denconst[Hsz];     // cmt + gl + eps + sum(|cs_rec|) + sum(|cs_sens|)
__device__ float   g_cmt[Hsz];
__device__ uint32_t g_pwT[Hsz*Hsz/2];   // phase_W row h, packed bf16x2 pairs, layout [k2][h]
__device__ uint32_t g_saT[Hsz*Hsz/2];   // sa_W    row h, packed bf16x2 pairs, layout [k2][h]
__device__ float   g_numbase[Bsz*Ssz*Hsz];  // per-(b,s,h) folded numerator base
__device__ float   g_denbase[Bsz*Ssz*Hsz];  // per-(b,s,h) folded denominator base

// ---------------- helpers ----------------
__device__ __forceinline__ float sp(float x) { return log1pf(expf(x)); }          // softplus (prep only)
__device__ __forceinline__ float tanhap(float x) {
    float y; asm("tanh.approx.f32 %0, %1;" : "=f"(y) : "f"(x)); return y;
}
__device__ __forceinline__ float fabsb(float x) {                                  // abs via ALU pipe (LOP3)
    return __int_as_float(__float_as_int(x) & 0x7fffffff);
}

// ---------------- kernel A: per-edge param folding ----------------
__global__ void prep_kernel(const float* __restrict__ sigma, const float* __restrict__ mu,
                            const float* __restrict__ w,     const float* __restrict__ erev,
                            const float* __restrict__ s_sigma, const float* __restrict__ s_mu,
                            const float* __restrict__ s_w,   const float* __restrict__ s_erev,
                            const float* __restrict__ input_w, const float* __restrict__ input_b)
{
    int r = blockIdx.x, h = threadIdx.x;
    if (r < Hsz) {                       // recurrent row (src j = r)
        int idx = r*Hsz + h;
        float a = 0.5f * sigma[idx];
        g_rab[idx] = make_float2(a, -a * mu[idx]);
        g_rcs[idx] = 0.5f * sp(w[idx]) * erev[idx];
    } else {                             // sensory row (i = r - Hsz)
        int i = r - Hsz;
        int idx = i*Hsz + h;
        float a = 0.5f * s_sigma[idx];
        // arg/2 = a*(x*iw + ib - mu) = (a*iw)*x + a*(ib - mu)
        g_sab[idx] = make_float2(a * input_w[i], a * (input_b[i] - s_mu[idx]));
        g_scs[idx] = 0.5f * sp(s_w[idx]) * s_erev[idx];
    }
}

// ---------------- kernel A2: per-h constants + bf16 transposed matmul weights ----------------
__global__ void prep2_kernel(const float* __restrict__ gleak, const float* __restrict__ vleak,
                             const float* __restrict__ cm,
                             const float* __restrict__ phase_W, const float* __restrict__ sa_W)
{
    int h = threadIdx.x;
    float nc = 0.f, dc = 0.f;
    for (int j = 0; j < Hsz; j++) { float cs = g_rcs[j*Hsz + h]; nc += cs; dc += fabsf(cs); }
    for (int i = 0; i < Isz; i++) { float cs = g_scs[i*Hsz + h]; nc += cs; dc += fabsf(cs); }
    float gl  = sp(gleak[h]);
    float cmt = sp(cm[h]) * (float)UNF;          // softplus(cm) * UNFOLDS / DT (DT=1)
    g_numconst[h] = gl * vleak[h] + nc;
    g_denconst[h] = cmt + gl + 1e-8f + dc;
    g_cmt[h] = cmt;
    for (int k2 = 0; k2 < Hsz/2; k2++) {
        __nv_bfloat162 p, q;
        p.x = __float2bfloat16(phase_W[h*Hsz + 2*k2]);
        p.y = __float2bfloat16(phase_W[h*Hsz + 2*k2 + 1]);
        q.x = __float2bfloat16(sa_W[h*Hsz + 2*k2]);
        q.y = __float2bfloat16(sa_W[h*Hsz + 2*k2 + 1]);
        g_pwT[k2*Hsz + h] = *reinterpret_cast<uint32_t*>(&p);
        g_saT[k2*Hsz + h] = *reinterpret_cast<uint32_t*>(&q);
    }
}

// ---------------- kernel B: sensory pre-pass (fully parallel over b,s) ----------------
__global__ __launch_bounds__(128, 1) void sens_kernel(const float* __restrict__ x)
{
    extern __shared__ float sm[];
    float2* sab = (float2*)sm;                 // 16384 float2 = 128KB
    float*  xs  = sm + 2*Isz*Hsz;              // 128 floats
    int h = threadIdx.x;

    #pragma unroll 4
    for (int r = 0; r < Isz; r++) sab[r*Hsz + h] = g_sab[r*Hsz + h];

    float scs[Isz];
    #pragma unroll
    for (int i = 0; i < Isz; i++) scs[i] = g_scs[i*Hsz + h];

    float ncst = g_numconst[h], dcst = g_denconst[h];
    int s = blockIdx.x;

    for (int bb = 0; bb < 16; bb++) {
        int b = blockIdx.y * 16 + bb;
        __syncthreads();
        xs[h] = x[(b*Ssz + s)*Isz + h];
        __syncthreads();
        float n = ncst, d = dcst;
        #pragma unroll
        for (int i4 = 0; i4 < Isz/4; i4++) {
            float4 x4 = *(const float4*)(xs + 4*i4);
            float xv[4] = {x4.x, x4.y, x4.z, x4.w};
            #pragma unroll
            for (int e = 0; e < 4; e++) {
                int i = 4*i4 + e;
                float2 p = sab[i*Hsz + h];
                float t = tanhap(fmaf(p.x, xv[e], p.y));
                n = fmaf(scs[i], t, n);
                d = fmaf(fabsb(scs[i]), t, d);
            }
        }
        int o = (b*Ssz + s)*Hsz + h;
        g_numbase[o] = n;
        g_denbase[o] = d;
    }
}

// ---------------- kernel C: sequential scan, 1 CTA per batch ----------------
__global__ __launch_bounds__(128, 1) void seq_kernel(
    const float* __restrict__ h0, const float* __restrict__ amplitude,
    const float* __restrict__ omega, const float* __restrict__ phase_b,
    const float* __restrict__ alpha_p, const float* __restrict__ beta_p,
    float* __restrict__ out, int write_hfinal)
{
    extern __shared__ float sm[];
    float2*   rab  = (float2*)sm;                       // [16384] float2 = 131072 B
    float*    vbuf = sm + 32768;                        // double buffer: 2x128 floats
    float*    sgv  = sm + 32768 + 256;                  // 128 floats
    uint32_t* pw   = (uint32_t*)(sm + 33152);           // 8192 u32 (bf16x2)
    uint32_t* sa   = pw + 8192;                         // 8192 u32

    int b = blockIdx.x, h = threadIdx.x;

    #pragma unroll 4
    for (int r = 0; r < Hsz; r++) rab[r*Hsz + h] = g_rab[r*Hsz + h];
    #pragma unroll 4
    for (int r = 0; r < Hsz/2; r++) { pw[r*Hsz + h] = g_pwT[r*Hsz + h]; sa[r*Hsz + h] = g_saT[r*Hsz + h]; }

    float csr[Hsz];
    #pragma unroll
    for (int j = 0; j < Hsz; j++) csr[j] = g_rcs[j*Hsz + h];

    float cmt = g_cmt[h];
    float aa  = alpha_p[0] * amplitude[h];
    float om  = omega[h];
    float pb  = phase_b[h];
    float bet = beta_p[0];

    float v = h0[b*Hsz + h];
    vbuf[h] = v;
    int cur = 0;
    __syncthreads();

    int base = b * Ssz * Hsz + h;
    float nb = g_numbase[base], db = g_denbase[base];

    for (int s = 0; s < Ssz; s++) {
        // prefetch next step's folded base terms (hides DRAM latency behind the unfolds)
        float nb_n = 0.f, db_n = 0.f;
        if (s + 1 < Ssz) {
            nb_n = g_numbase[base + (s+1)*Hsz];
            db_n = g_denbase[base + (s+1)*Hsz];
        }

        #pragma unroll 1
        for (int u = 0; u < UNF; u++) {
            const float* vc = vbuf + cur*Hsz;
            float num = nb, den = db;
            #pragma unroll
            for (int j4 = 0; j4 < Hsz/4; j4++) {
                float4 v4 = *(const float4*)(vc + 4*j4);
                float vv[4] = {v4.x, v4.y, v4.z, v4.w};
                #pragma unroll
                for (int e = 0; e < 4; e++) {
                    int j = 4*j4 + e;
                    float2 p = rab[j*Hsz + h];
                    float t = tanhap(fmaf(p.x, vv[e], p.y));
                    num = fmaf(csr[j], t, num);
                    den = fmaf(fabsb(csr[j]), t, den);
                }
            }
            v = __fdividef(fmaf(cmt, v, num), den);
            vbuf[(cur ^ 1)*Hsz + h] = v;
            __syncthreads();
            cur ^= 1;
        }

        // oscillatory pulse: v += alpha*amplitude*sin(omega*t + v@phase_W.T + phase_b)
        const float* vc = vbuf + cur*Hsz;
        float phi = pb;
        #pragma unroll 8
        for (int k2 = 0; k2 < Hsz/2; k2++) {
            uint32_t u32 = pw[k2*Hsz + h];
            float2 wv = __bfloat1622float2(*reinterpret_cast<__nv_bfloat162*>(&u32));
            float2 vp = *(const float2*)(vc + 2*k2);
            phi = fmaf(wv.x, vp.x, phi);
            phi = fmaf(wv.y, vp.y, phi);
        }
        v += aa * __sinf(fmaf(om, (float)s, phi));

        // self-attend: v += beta * (sigmoid(v) @ sa_W.T)
        sgv[h] = fmaf(0.5f, tanhap(0.5f * v), 0.5f);
        __syncthreads();
        float acc = 0.f;
        #pragma unroll 8
        for (int k2 = 0; k2 < Hsz/2; k2++) {
            uint32_t u32 = sa[k2*Hsz + h];
            float2 wv = __bfloat1622float2(*reinterpret_cast<__nv_bfloat162*>(&u32));
            float2 sv = *(const float2*)(sgv + 2*k2);
            acc = fmaf(wv.x, sv.x, acc);
            acc = fmaf(wv.y, sv.y, acc);
        }
        v = fmaf(bet, acc, v);

        out[(b*Ssz + s)*Hsz + h] = v;
        vbuf[cur*Hsz + h] = v;
        __syncthreads();

        nb = nb_n; db = db_n;
    }

    if (write_hfinal)
        out[Bsz*Ssz*Hsz + b*Hsz + h] = v;
}

// ---------------- launch ----------------
extern "C" void kernel_launch(void* const* d_in, const int* in_sizes, int n_in,
                              void* d_out, int out_size)
{
    const float* x        = (const float*)d_in[0];
    const float* h0       = (const float*)d_in[1];
    const float* input_w  = (const float*)d_in[2];
    const float* input_b  = (const float*)d_in[3];
    const float* gleak    = (const float*)d_in[4];
    const float* vleak    = (const float*)d_in[5];
    const float* cm       = (const float*)d_in[6];
    const float* sigma    = (const float*)d_in[7];
    const float* mu       = (const float*)d_in[8];
    const float* w        = (const float*)d_in[9];
    const float* erev     = (const float*)d_in[10];
    const float* s_sigma  = (const float*)d_in[11];
    const float* s_mu     = (const float*)d_in[12];
    const float* s_w      = (const float*)d_in[13];
    const float* s_erev   = (const float*)d_in[14];
    const float* amplitude= (const float*)d_in[15];
    const float* omega    = (const float*)d_in[16];
    const float* phase_W  = (const float*)d_in[17];
    const float* phase_b  = (const float*)d_in[18];
    const float* alpha    = (const float*)d_in[19];
    const float* sa_W     = (const float*)d_in[20];
    const float* beta     = (const float*)d_in[21];
    float* out = (float*)d_out;

    const int smem_sens = 2*Isz*Hsz*4 + Hsz*4;                       // 131584
    const int smem_seq  = Hsz*Hsz*8 + 256*4 + 128*4 + Hsz*Hsz*2*2;   // 198144
    cudaFuncSetAttribute(sens_kernel, cudaFuncAttributeMaxDynamicSharedMemorySize, smem_sens);
    cudaFuncSetAttribute(seq_kernel,  cudaFuncAttributeMaxDynamicSharedMemorySize, smem_seq);

    prep_kernel<<<Hsz + Isz, Hsz>>>(sigma, mu, w, erev, s_sigma, s_mu, s_w, s_erev, input_w, input_b);
    prep2_kernel<<<1, Hsz>>>(gleak, vleak, cm, phase_W, sa_W);

    dim3 gb(Ssz, Bsz/16);
    sens_kernel<<<gb, Hsz, smem_sens>>>(x);

    int whf = (out_size >= Bsz*Ssz*Hsz + Bsz*Hsz) ? 1 : 0;
    seq_kernel<<<Bsz, Hsz, smem_seq>>>(h0, amplitude, omega, phase_b, alpha, beta, out, whf);
}

// round 2
// speedup vs baseline: 1.9099x; 1.9099x over previous
#include <cuda_runtime.h>
#include <cuda_bf16.h>
#include <cstdint>

#define Bsz 64
#define Ssz 256
#define Isz 128
#define Hsz 128
#define UNF 6
#define TPB 512
#define NG  4
#define JPG 32

// ---------------- device scratch ----------------
__device__ float2  g_rab[Hsz*Hsz];      // recurrent (a,b): a=0.5*sigma, b=-0.5*sigma*mu, [src][dst]
__device__ float   g_rcs[Hsz*Hsz];      // recurrent signed weight 0.5*softplus(w)*erev, [src][dst]
__device__ float2  g_sab[Isz*Hsz];      // sensory (a',b') with input affine folded, [i][h]
__device__ float   g_scs[Isz*Hsz];      // sensory signed weight, [i][h]
__device__ float   g_numconst[Hsz];
__device__ float   g_denconst[Hsz];
__device__ float   g_cmt[Hsz];
__device__ uint32_t g_pwT[Hsz*Hsz/2];   // phase_W bf16x2, [k2][h]
__device__ uint32_t g_saT[Hsz*Hsz/2];   // sa_W bf16x2, [k2][h]
__device__ float   g_numbase[Bsz*Ssz*Hsz];
__device__ float   g_denbase[Bsz*Ssz*Hsz];

// ---------------- helpers ----------------
__device__ __forceinline__ float sp(float x) { return log1pf(expf(x)); }
__device__ __forceinline__ float tanhap(float x) {
    float y; asm("tanh.approx.f32 %0, %1;" : "=f"(y) : "f"(x)); return y;
}
__device__ __forceinline__ float fabsb(float x) {
    return __int_as_float(__float_as_int(x) & 0x7fffffff);
}

// ---------------- kernel A: per-edge param folding ----------------
__global__ void prep_kernel(const float* __restrict__ sigma, const float* __restrict__ mu,
                            const float* __restrict__ w,     const float* __restrict__ erev,
                            const float* __restrict__ s_sigma, const float* __restrict__ s_mu,
                            const float* __restrict__ s_w,   const float* __restrict__ s_erev,
                            const float* __restrict__ input_w, const float* __restrict__ input_b)
{
    int r = blockIdx.x, h = threadIdx.x;
    if (r < Hsz) {
        int idx = r*Hsz + h;
        float a = 0.5f * sigma[idx];
        g_rab[idx] = make_float2(a, -a * mu[idx]);
        g_rcs[idx] = 0.5f * sp(w[idx]) * erev[idx];
    } else {
        int i = r - Hsz;
        int idx = i*Hsz + h;
        float a = 0.5f * s_sigma[idx];
        g_sab[idx] = make_float2(a * input_w[i], a * (input_b[i] - s_mu[idx]));
        g_scs[idx] = 0.5f * sp(s_w[idx]) * s_erev[idx];
    }
}

// ---------------- kernel A2: per-h constants + bf16 matmul weights ----------------
__global__ void prep2_kernel(const float* __restrict__ gleak, const float* __restrict__ vleak,
                             const float* __restrict__ cm,
                             const float* __restrict__ phase_W, const float* __restrict__ sa_W)
{
    int h = threadIdx.x;
    float nc = 0.f, dc = 0.f;
    for (int j = 0; j < Hsz; j++) { float cs = g_rcs[j*Hsz + h]; nc += cs; dc += fabsf(cs); }
    for (int i = 0; i < Isz; i++) { float cs = g_scs[i*Hsz + h]; nc += cs; dc += fabsf(cs); }
    float gl  = sp(gleak[h]);
    float cmt = sp(cm[h]) * (float)UNF;
    g_numconst[h] = gl * vleak[h] + nc;
    g_denconst[h] = cmt + gl + 1e-8f + dc;
    g_cmt[h] = cmt;
    for (int k2 = 0; k2 < Hsz/2; k2++) {
        __nv_bfloat162 p, q;
        p.x = __float2bfloat16(phase_W[h*Hsz + 2*k2]);
        p.y = __float2bfloat16(phase_W[h*Hsz + 2*k2 + 1]);
        q.x = __float2bfloat16(sa_W[h*Hsz + 2*k2]);
        q.y = __float2bfloat16(sa_W[h*Hsz + 2*k2 + 1]);
        g_pwT[k2*Hsz + h] = *reinterpret_cast<uint32_t*>(&p);
        g_saT[k2*Hsz + h] = *reinterpret_cast<uint32_t*>(&q);
    }
}

// ---------------- kernel B: sensory pre-pass (512 thr, src-split) ----------------
__global__ __launch_bounds__(TPB, 1) void sens_kernel(const float* __restrict__ x)
{
    extern __shared__ float sm[];
    float2* sab = (float2*)sm;            // 16384 f2 = 131072 B
    float*  xs  = sm + 2*Isz*Hsz;         // 128
    float*  pn  = xs + 128;               // 512
    float*  pd  = pn + 512;               // 512

    int tid = threadIdx.x;
    int h = tid & 127, g = tid >> 7;

    for (int r = tid; r < Isz*Hsz; r += TPB) sab[r] = g_sab[r];

    float scs[JPG];
    #pragma unroll
    for (int il = 0; il < JPG; il++) scs[il] = g_scs[(g*JPG + il)*Hsz + h];

    float ncst = g_numconst[h], dcst = g_denconst[h];
    int s = blockIdx.x;

    for (int bb = 0; bb < 16; bb++) {
        int b = blockIdx.y * 16 + bb;
        __syncthreads();
        if (tid < Isz) xs[h] = x[(b*Ssz + s)*Isz + h];
        __syncthreads();
        float n = 0.f, d = 0.f;
        #pragma unroll
        for (int q = 0; q < JPG/4; q++) {
            float4 x4 = *(const float4*)(xs + g*JPG + 4*q);
            float xv[4] = {x4.x, x4.y, x4.z, x4.w};
            #pragma unroll
            for (int e = 0; e < 4; e++) {
                int il = 4*q + e;
                float2 p = sab[(g*JPG + il)*Hsz + h];
                float t = tanhap(fmaf(p.x, xv[e], p.y));
                n = fmaf(scs[il], t, n);
                d = fmaf(fabsb(scs[il]), t, d);
            }
        }
        pn[g*Hsz + h] = n; pd[g*Hsz + h] = d;
        __syncthreads();
        if (g == 0) {
            float num = ncst + pn[h] + pn[Hsz + h] + pn[2*Hsz + h] + pn[3*Hsz + h];
            float den = dcst + pd[h] + pd[Hsz + h] + pd[2*Hsz + h] + pd[3*Hsz + h];
            int o = (b*Ssz + s)*Hsz + h;
            g_numbase[o] = num;
            g_denbase[o] = den;
        }
    }
}

// ---------------- kernel C: sequential scan (512 thr, src-split) ----------------
__global__ __launch_bounds__(TPB, 1) void seq_kernel(
    const float* __restrict__ h0, const float* __restrict__ amplitude,
    const float* __restrict__ omega, const float* __restrict__ phase_b,
    const float* __restrict__ alpha_p, const float* __restrict__ beta_p,
    float* __restrict__ out, int write_hfinal)
{
    extern __shared__ float sm[];
    float2*   rab  = (float2*)sm;                 // 16384 f2 = 131072 B
    float*    vbuf = sm + 32768;                  // 128
    float*    sgv  = vbuf + 128;                  // 128
    float*    pnum = sgv + 128;                   // 512
    float*    pden = pnum + 512;                  // 512
    float*    pph  = pden + 512;                  // 512
    float*    psa  = pph + 512;                   // 512
    uint32_t* pw   = (uint32_t*)(psa + 512);      // 8192 u32
    uint32_t* sa   = pw + 8192;                   // 8192 u32

    int b = blockIdx.x;
    int tid = threadIdx.x;
    int h = tid & 127, g = tid >> 7;

    for (int r = tid; r < Hsz*Hsz; r += TPB) rab[r] = g_rab[r];
    for (int r = tid; r < Hsz*Hsz/2; r += TPB) { pw[r] = g_pwT[r]; sa[r] = g_saT[r]; }

    float csr[JPG];
    #pragma unroll
    for (int jl = 0; jl < JPG; jl++) csr[jl] = g_rcs[(g*JPG + jl)*Hsz + h];

    float cmt = g_cmt[h];
    float aa  = alpha_p[0] * amplitude[h];
    float om  = omega[h];
    float pb  = phase_b[h];
    float bet = beta_p[0];

    float v = h0[b*Hsz + h];
    if (g == 0) vbuf[h] = v;
    __syncthreads();

    int base = b * Ssz * Hsz + h;
    float nb = g_numbase[base], db = g_denbase[base];

    for (int s = 0; s < Ssz; s++) {
        float nb_n = 0.f, db_n = 0.f;
        if (s + 1 < Ssz) {
            nb_n = g_numbase[base + (s+1)*Hsz];
            db_n = g_denbase[base + (s+1)*Hsz];
        }

        #pragma unroll 1
        for (int u = 0; u < UNF; u++) {
            float n = 0.f, d = 0.f;
            #pragma unroll
            for (int q = 0; q < JPG/4; q++) {
                float4 v4 = *(const float4*)(vbuf + g*JPG + 4*q);
                float vv[4] = {v4.x, v4.y, v4.z, v4.w};
                #pragma unroll
                for (int e = 0; e < 4; e++) {
                    int jl = 4*q + e;
                    float2 p = rab[(g*JPG + jl)*Hsz + h];
                    float t = tanhap(fmaf(p.x, vv[e], p.y));
                    n = fmaf(csr[jl], t, n);
                    d = fmaf(fabsb(csr[jl]), t, d);
                }
            }
            pnum[g*Hsz + h] = n; pden[g*Hsz + h] = d;
            __syncthreads();
            float num = nb + pnum[h] + pnum[Hsz + h] + pnum[2*Hsz + h] + pnum[3*Hsz + h];
            float den = db + pden[h] + pden[Hsz + h] + pden[2*Hsz + h] + pden[3*Hsz + h];
            v = __fdividef(fmaf(cmt, v, num), den);
            if (g == 0) vbuf[h] = v;
            __syncthreads();
        }

        // pulse: phi = v @ phase_W.T + phase_b (split over k)
        float php = (g == 0) ? pb : 0.f;
        #pragma unroll
        for (int k2 = 0; k2 < JPG/2; k2++) {
            uint32_t u32 = pw[(g*(JPG/2) + k2)*Hsz + h];
            float2 wv = __bfloat1622float2(*reinterpret_cast<__nv_bfloat162*>(&u32));
            float2 vp = *(const float2*)(vbuf + g*JPG + 2*k2);
            php = fmaf(wv.x, vp.x, php);
            php = fmaf(wv.y, vp.y, php);
        }
        pph[g*Hsz + h] = php;
        __syncthreads();
        float phi = pph[h] + pph[Hsz + h] + pph[2*Hsz + h] + pph[3*Hsz + h];
        v += aa * __sinf(fmaf(om, (float)s, phi));
        if (g == 0) sgv[h] = fmaf(0.5f, tanhap(0.5f * v), 0.5f);
        __syncthreads();

        // self-attend: v += beta * (sigmoid(v) @ sa_W.T) (split over k)
        float accp = 0.f;
        #pragma unroll
        for (int k2 = 0; k2 < JPG/2; k2++) {
            uint32_t u32 = sa[(g*(JPG/2) + k2)*Hsz + h];
            float2 wv = __bfloat1622float2(*reinterpret_cast<__nv_bfloat162*>(&u32));
            float2 sv = *(const float2*)(sgv + g*JPG + 2*k2);
            accp = fmaf(wv.x, sv.x, accp);
            accp = fmaf(wv.y, sv.y, accp);
        }
        psa[g*Hsz + h] = accp;
        __syncthreads();
        float acc = psa[h] + psa[Hsz + h] + psa[2*Hsz + h] + psa[3*Hsz + h];
        v = fmaf(bet, acc, v);
        if (g == 0) {
            out[(b*Ssz + s)*Hsz + h] = v;
            vbuf[h] = v;
        }
        __syncthreads();

        nb = nb_n; db = db_n;
    }

    if (write_hfinal && g == 0)
        out[Bsz*Ssz*Hsz + b*Hsz + h] = v;
}

// ---------------- launch ----------------
extern "C" void kernel_launch(void* const* d_in, const int* in_sizes, int n_in,
                              void* d_out, int out_size)
{
    const float* x        = (const float*)d_in[0];
    const float* h0       = (const float*)d_in[1];
    const float* input_w  = (const float*)d_in[2];
    const float* input_b  = (const float*)d_in[3];
    const float* gleak    = (const float*)d_in[4];
    const float* vleak    = (const float*)d_in[5];
    const float* cm       = (const float*)d_in[6];
    const float* sigma    = (const float*)d_in[7];
    const float* mu       = (const float*)d_in[8];
    const float* w        = (const float*)d_in[9];
    const float* erev     = (const float*)d_in[10];
    const float* s_sigma  = (const float*)d_in[11];
    const float* s_mu     = (const float*)d_in[12];
    const float* s_w      = (const float*)d_in[13];
    const float* s_erev   = (const float*)d_in[14];
    const float* amplitude= (const float*)d_in[15];
    const float* omega    = (const float*)d_in[16];
    const float* phase_W  = (const float*)d_in[17];
    const float* phase_b  = (const float*)d_in[18];
    const float* alpha    = (const float*)d_in[19];
    const float* sa_W     = (const float*)d_in[20];
    const float* beta     = (const float*)d_in[21];
    float* out = (float*)d_out;

    const int smem_sens = 2*Isz*Hsz*4 + (128 + 512 + 512)*4;                 // 135680
    const int smem_seq  = Hsz*Hsz*8 + (128+128+512*4)*4 + Hsz*Hsz/2*4*2;     // 205824
    cudaFuncSetAttribute(sens_kernel, cudaFuncAttributeMaxDynamicSharedMemorySize, smem_sens);
    cudaFuncSetAttribute(seq_kernel,  cudaFuncAttributeMaxDynamicSharedMemorySize, smem_seq);

    prep_kernel<<<Hsz + Isz, Hsz>>>(sigma, mu, w, erev, s_sigma, s_mu, s_w, s_erev, input_w, input_b);
    prep2_kernel<<<1, Hsz>>>(gleak, vleak, cm, phase_W, sa_W);

    dim3 gb(Ssz, Bsz/16);
    sens_kernel<<<gb, TPB, smem_sens>>>(x);

    int whf = (out_size >= Bsz*Ssz*Hsz + Bsz*Hsz) ? 1 : 0;
    seq_kernel<<<Bsz, TPB, smem_seq>>>(h0, amplitude, omega, phase_b, alpha, beta, out, whf);
}